// round 9
// baseline (speedup 1.0000x reference)
#include <cuda_runtime.h>
#include <cstdint>

#define EMBED 1024
#define NHEAD 16
#define HDIM  64
#define BATCH 4
#define SEQ   2048
#define MTOT  (BATCH*SEQ)      /* 8192 */
#define QKVF  (3*EMBED)        /* 3072 */

// Scratch (device globals: allocation-free per harness rules)
__device__ float g_qkv[(size_t)MTOT * QKVF];   // [M, 3C]
__device__ float g_att[(size_t)MTOT * EMBED];  // [M, C]

__device__ __forceinline__ uint32_t f2tf32(float f) {
  uint32_t u;
  asm("cvt.rna.tf32.f32 %0, %1;" : "=r"(u) : "f"(f));
  return u;
}

__device__ __forceinline__ void mma_tf32(float c[4], const uint4& a, const uint2& b) {
  asm volatile(
    "mma.sync.aligned.m16n8k8.row.col.f32.tf32.tf32.f32 "
    "{%0,%1,%2,%3}, {%4,%5,%6,%7}, {%8,%9}, {%0,%1,%2,%3};\n"
    : "+f"(c[0]), "+f"(c[1]), "+f"(c[2]), "+f"(c[3])
    : "r"(a.x), "r"(a.y), "r"(a.z), "r"(a.w), "r"(b.x), "r"(b.y));
}

__device__ __forceinline__ uint32_t smem_u32(const void* p) {
  uint32_t a;
  asm("{ .reg .u64 t; cvta.to.shared.u64 t, %1; cvt.u32.u64 %0, t; }"
      : "=r"(a) : "l"(p));
  return a;
}

__device__ __forceinline__ void cp16(uint32_t dst, const void* src) {
  asm volatile("cp.async.ca.shared.global [%0], [%1], 16;"
               :: "r"(dst), "l"(src) : "memory");
}

// ldmatrix x4 (b16 mode; for 32-bit tf32 data each 8x8-b16 matrix = 8x4 words)
__device__ __forceinline__ void ldsm4(uint4& d, uint32_t addr) {
  asm volatile("ldmatrix.sync.aligned.m8n8.x4.shared.b16 {%0,%1,%2,%3}, [%4];"
               : "=r"(d.x), "=r"(d.y), "=r"(d.z), "=r"(d.w) : "r"(addr));
}

// ===========================================================================
// TF32 GEMM: C[M,N] = A[M,K] @ B[N,K]^T + bias[N]
// CTA 128x128x32, 128 threads = 4 warps of 64x64. cp.async 2-stage ring
// (73.7KB smem -> 3 CTAs/SM), ldmatrix fragment loads, read-side cvt.rna.
// Smem stride 36 words: LDSM rows hit banks 4r -> conflict-free.
// ===========================================================================
#define GSTRW 36
#define GTILEW (128 * GSTRW)         /* 4608 words per operand tile */
#define GSTAGEW (2 * GTILEW)         /* 9216 words per stage (A+B) */
#define GSMEM_BYTES (2 * GSTAGEW * 4)   /* 73728 B */

__global__ __launch_bounds__(128, 3) void gemm_cpa(
    const float* __restrict__ A, const float* __restrict__ Bm,
    const float* __restrict__ bias, float* __restrict__ C,
    int M, int N, int K)
{
  extern __shared__ float gsm[];
  const uint32_t sb = smem_u32(gsm);

  const int tid  = threadIdx.x;
  const int lane = tid & 31;
  const int wid  = tid >> 5;
  const int wm   = wid & 1;          // 64-row strip
  const int wn   = wid >> 1;         // 64-col strip
  const int m0   = blockIdx.y * 128;
  const int n0   = blockIdx.x * 128;
  const int r0   = lane >> 2;
  const int tq   = lane & 3;

  // ldmatrix per-lane address offsets (bytes)
  // A a-frag: m0:rows0-7/k0-3  m1:rows8-15/k0-3  m2:rows0-7/k4-7  m3:rows8-15/k4-7
  const uint32_t a_lane = (uint32_t)(((lane & 7) * GSTRW +
                          ((lane >> 3) & 1) * 8 * GSTRW + (lane >> 4) * 4) * 4);
  // B b-frag pair: m0:k0-3  m1:k4-7  m2:k8-11  m3:k12-15 (same 8 n-rows)
  const uint32_t b_lane = (uint32_t)(((lane & 7) * GSTRW + (lane >> 3) * 4) * 4);

  float acc[4][8][4];
  #pragma unroll
  for (int i = 0; i < 4; i++)
    #pragma unroll
    for (int j = 0; j < 8; j++)
      #pragma unroll
      for (int r = 0; r < 4; r++) acc[i][j][r] = 0.0f;

  auto fill = [&](int s, int k0) {
    const uint32_t base = sb + (uint32_t)s * GSTAGEW * 4;
    #pragma unroll
    for (int i = 0; i < 8; i++) {
      int idx = tid + 128 * i;
      int row = idx >> 3, g = idx & 7;
      uint32_t off = (uint32_t)(row * GSTRW + g * 4) * 4;
      cp16(base + off,              A  + (size_t)(m0 + row) * K + k0 + g * 4);
      cp16(base + GTILEW * 4 + off, Bm + (size_t)(n0 + row) * K + k0 + g * 4);
    }
    asm volatile("cp.async.commit_group;" ::: "memory");
  };

  auto compute = [&](int s) {
    const uint32_t As = sb + (uint32_t)s * GSTAGEW * 4 + (uint32_t)(wm * 64 * GSTRW) * 4;
    const uint32_t Bs = sb + (uint32_t)s * GSTAGEW * 4 + GTILEW * 4 +
                        (uint32_t)(wn * 64 * GSTRW) * 4;
    #pragma unroll
    for (int p = 0; p < 2; p++) {        // kt pair: kt = 2p, 2p+1
      uint4 af[2][4];
      #pragma unroll
      for (int half = 0; half < 2; half++)
        #pragma unroll
        for (int mf = 0; mf < 4; mf++) {
          uint4 raw;
          ldsm4(raw, As + a_lane +
                     (uint32_t)((mf * 16 * GSTRW + (2 * p + half) * 8) * 4));
          af[half][mf].x = f2tf32(__uint_as_float(raw.x));
          af[half][mf].y = f2tf32(__uint_as_float(raw.y));
          af[half][mf].z = f2tf32(__uint_as_float(raw.z));
          af[half][mf].w = f2tf32(__uint_as_float(raw.w));
        }
      #pragma unroll
      for (int nt = 0; nt < 8; nt++) {
        uint4 braw;
        ldsm4(braw, Bs + b_lane + (uint32_t)((nt * 8 * GSTRW + p * 16) * 4));
        uint2 bf0 = make_uint2(f2tf32(__uint_as_float(braw.x)),
                               f2tf32(__uint_as_float(braw.y)));
        uint2 bf1 = make_uint2(f2tf32(__uint_as_float(braw.z)),
                               f2tf32(__uint_as_float(braw.w)));
        #pragma unroll
        for (int mf = 0; mf < 4; mf++) {
          mma_tf32(acc[mf][nt], af[0][mf], bf0);
          mma_tf32(acc[mf][nt], af[1][mf], bf1);
        }
      }
    }
  };

  const int nk = K >> 5;
  fill(0, 0);

  for (int t = 0; t < nk; t++) {
    if (t + 1 < nk) {
      fill((t + 1) & 1, (t + 1) << 5);
      asm volatile("cp.async.wait_group 1;" ::: "memory");
    } else {
      asm volatile("cp.async.wait_group 0;" ::: "memory");
    }
    __syncthreads();
    compute(t & 1);
    __syncthreads();
  }

  const int gn_base = n0 + wn * 64 + (tq << 1);
  #pragma unroll
  for (int mf = 0; mf < 4; mf++) {
    int gm = m0 + wm * 64 + mf * 16 + r0;
    #pragma unroll
    for (int nt = 0; nt < 8; nt++) {
      int gn = gn_base + nt * 8;
      float b0 = bias[gn], b1 = bias[gn + 1];
      float2 v0 = make_float2(acc[mf][nt][0] + b0, acc[mf][nt][1] + b1);
      float2 v1 = make_float2(acc[mf][nt][2] + b0, acc[mf][nt][3] + b1);
      *(float2*)(C + (size_t)gm * N + gn)       = v0;
      *(float2*)(C + (size_t)(gm + 8) * N + gn) = v1;
    }
  }
}

// ===========================================================================
// Flash attention, TF32 mma.sync, 128 threads = 4 warps of 32q x 64k tiles.
// ldmatrix for K b-frags (x4 = 2 k-steps) and P a-frags; V scalar LDS.
// ===========================================================================
#define FQF 0
#define FKT 8192
#define FVS (8192 + 64*68)
#define FPS (8192 + 64*68 + 64*72)
#define FTOT (8192 + 64*68 + 64*72 + 128*68)   /* 25856 words = 103424 B */

__global__ __launch_bounds__(128) void flash_tc(
    const float* __restrict__ qkv, float* __restrict__ out)
{
  extern __shared__ uint32_t sm[];
  uint32_t* QF = sm + FQF;
  uint32_t* Kt = sm + FKT;
  uint32_t* Vs = sm + FVS;
  uint32_t* Ps = sm + FPS;
  const uint32_t sbase = smem_u32(sm);
  const uint32_t KtB = sbase + FKT * 4;
  const uint32_t PsB = sbase + FPS * 4;

  const int tid  = threadIdx.x;
  const int lane = tid & 31;
  const int w    = tid >> 5;
  const int bx   = blockIdx.x;
  const int bh   = blockIdx.y;
  const int b    = bh >> 4;
  const int h    = bh & 15;
  const int q0   = bx * 128;

  const float* qbase = qkv + ((size_t)b * SEQ + q0) * QKVF + h * HDIM;
  const float* kbase = qkv + ((size_t)b * SEQ) * QKVF + EMBED + h * HDIM;
  const float* vbase = kbase + EMBED;

  // K b-frag lane offset: m0:k0-3 m1:k4-7 m2:k8-11 m3:k12-15 (rows = keys)
  const uint32_t kb_lane = (uint32_t)(((lane & 7) * 68 + (lane >> 3) * 4) * 4);
  // P a-frag lane offset: m0:r0-7/k0-3 m1:r8-15/k0-3 m2:r0-7/k4-7 m3:r8-15/k4-7
  const uint32_t pa_lane = (uint32_t)(((lane & 7) * 68 +
                           ((lane >> 3) & 1) * 8 * 68 + (lane >> 4) * 4) * 4);

  // ---- Q scatter into fragment layout (once per block), scaled by 1/8 ----
  for (int e = tid; e < 128 * 16; e += 128) {
    int r = e >> 4, d4 = (e & 15) << 2;
    float4 qv = *(const float4*)(qbase + (size_t)r * QKVF + d4);
    float qf[4] = {qv.x, qv.y, qv.z, qv.w};
    int wq = r >> 5, m = (r >> 4) & 1, rr = r & 15;
    #pragma unroll
    for (int j = 0; j < 4; j++) {
      int d = d4 + j, ks = d >> 3, dd = d & 7;
      int ln = ((rr & 7) << 2) | (dd & 3);
      int rg = (rr >> 3) | ((dd >> 2) << 1);
      QF[(((((wq << 1) | m) << 3 | ks) << 5 | ln) << 2) | rg] = f2tf32(qf[j] * 0.125f);
    }
  }

  const int r0 = lane >> 2;
  const int tq = lane & 3;
  const int qmin = q0 + w * 32;
  const int qmax = qmin + 31;
  const int qg[2] = { qmin + r0, qmin + 16 + r0 };

  float mrow[2][2], lrow[2][2];
  #pragma unroll
  for (int m = 0; m < 2; m++) {
    mrow[m][0] = mrow[m][1] = -1e30f;
    lrow[m][0] = lrow[m][1] = 0.0f;
  }
  float o[2][8][4];
  #pragma unroll
  for (int m = 0; m < 2; m++)
    #pragma unroll
    for (int nt = 0; nt < 8; nt++)
      #pragma unroll
      for (int j = 0; j < 4; j++) o[m][nt][j] = 0.0f;

  const int nkv = 2 * bx + 2;
  for (int kv = 0; kv < nkv; kv++) {
    const int k0 = kv * 64;
    __syncthreads();
    for (int e = tid; e < 64 * 16; e += 128) {
      int r = e >> 4, d4 = (e & 15) << 2;
      float4 kf4 = *(const float4*)(kbase + (size_t)(k0 + r) * QKVF + d4);
      float4 vf4 = *(const float4*)(vbase + (size_t)(k0 + r) * QKVF + d4);
      uint4 ku = make_uint4(f2tf32(kf4.x), f2tf32(kf4.y), f2tf32(kf4.z), f2tf32(kf4.w));
      uint4 vu = make_uint4(f2tf32(vf4.x), f2tf32(vf4.y), f2tf32(vf4.z), f2tf32(vf4.w));
      *(uint4*)&Kt[r * 68 + d4] = ku;
      *(uint4*)&Vs[r * 72 + d4] = vu;
    }
    __syncthreads();

    if (k0 > qmax) continue;

    // ---- S = Q @ K^T (ldmatrix K b-frags: one x4 per (nt, ks-pair)) ----
    float s[2][8][4];
    #pragma unroll
    for (int m = 0; m < 2; m++)
      #pragma unroll
      for (int nt = 0; nt < 8; nt++)
        s[m][nt][0] = s[m][nt][1] = s[m][nt][2] = s[m][nt][3] = 0.0f;

    #pragma unroll
    for (int p = 0; p < 4; p++) {        // ks = 2p, 2p+1
      uint4 qaA0 = *(const uint4*)&QF[((((w << 1) << 3 | (2*p)) << 5 | lane) << 2)];
      uint4 qaA1 = *(const uint4*)&QF[(((((w << 1) | 1) << 3 | (2*p)) << 5 | lane) << 2)];
      uint4 qaB0 = *(const uint4*)&QF[((((w << 1) << 3 | (2*p+1)) << 5 | lane) << 2)];
      uint4 qaB1 = *(const uint4*)&QF[(((((w << 1) | 1) << 3 | (2*p+1)) << 5 | lane) << 2)];
      #pragma unroll
      for (int nt = 0; nt < 8; nt++) {
        uint4 kraw;
        ldsm4(kraw, KtB + kb_lane + (uint32_t)((nt * 8 * 68 + p * 16) * 4));
        uint2 bk0 = make_uint2(kraw.x, kraw.y);
        uint2 bk1 = make_uint2(kraw.z, kraw.w);
        mma_tf32(s[0][nt], qaA0, bk0);
        mma_tf32(s[1][nt], qaA1, bk0);
        mma_tf32(s[0][nt], qaB0, bk1);
        mma_tf32(s[1][nt], qaB1, bk1);
      }
    }

    // ---- causal mask ----
    if (k0 + 63 > qmin) {
      #pragma unroll
      for (int m = 0; m < 2; m++) {
        #pragma unroll
        for (int nt = 0; nt < 8; nt++) {
          int c0 = k0 + 8 * nt + 2 * tq;
          int c1 = c0 + 1;
          if (c0 > qg[m])     s[m][nt][0] = -1e30f;
          if (c1 > qg[m])     s[m][nt][1] = -1e30f;
          if (c0 > qg[m] + 8) s[m][nt][2] = -1e30f;
          if (c1 > qg[m] + 8) s[m][nt][3] = -1e30f;
        }
      }
    }

    // ---- online softmax per m-frag ----
    #pragma unroll
    for (int m = 0; m < 2; m++) {
      float mx0 = -1e30f, mx1 = -1e30f;
      #pragma unroll
      for (int nt = 0; nt < 8; nt++) {
        mx0 = fmaxf(mx0, fmaxf(s[m][nt][0], s[m][nt][1]));
        mx1 = fmaxf(mx1, fmaxf(s[m][nt][2], s[m][nt][3]));
      }
      mx0 = fmaxf(mx0, __shfl_xor_sync(0xffffffffu, mx0, 1));
      mx0 = fmaxf(mx0, __shfl_xor_sync(0xffffffffu, mx0, 2));
      mx1 = fmaxf(mx1, __shfl_xor_sync(0xffffffffu, mx1, 1));
      mx1 = fmaxf(mx1, __shfl_xor_sync(0xffffffffu, mx1, 2));

      float mn0 = fmaxf(mrow[m][0], mx0), mn1 = fmaxf(mrow[m][1], mx1);
      float a0 = __expf(mrow[m][0] - mn0), a1 = __expf(mrow[m][1] - mn1);
      mrow[m][0] = mn0; mrow[m][1] = mn1;

      const int prow = w * 32 + m * 16 + r0;
      float rs0 = 0.0f, rs1 = 0.0f;
      #pragma unroll
      for (int nt = 0; nt < 8; nt++) {
        float p0 = __expf(s[m][nt][0] - mn0);
        float p1 = __expf(s[m][nt][1] - mn0);
        float p2 = __expf(s[m][nt][2] - mn1);
        float p3 = __expf(s[m][nt][3] - mn1);
        rs0 += p0 + p1;
        rs1 += p2 + p3;
        *(uint2*)&Ps[prow * 68 + 8 * nt + 2 * tq]       = make_uint2(f2tf32(p0), f2tf32(p1));
        *(uint2*)&Ps[(prow + 8) * 68 + 8 * nt + 2 * tq] = make_uint2(f2tf32(p2), f2tf32(p3));
      }
      rs0 += __shfl_xor_sync(0xffffffffu, rs0, 1);
      rs0 += __shfl_xor_sync(0xffffffffu, rs0, 2);
      rs1 += __shfl_xor_sync(0xffffffffu, rs1, 1);
      rs1 += __shfl_xor_sync(0xffffffffu, rs1, 2);
      lrow[m][0] = lrow[m][0] * a0 + rs0;
      lrow[m][1] = lrow[m][1] * a1 + rs1;
      #pragma unroll
      for (int nt = 0; nt < 8; nt++) {
        o[m][nt][0] *= a0; o[m][nt][1] *= a0;
        o[m][nt][2] *= a1; o[m][nt][3] *= a1;
      }
    }

    __syncwarp();

    // ---- O += P @ V (ldmatrix P a-frags; scalar V b-frags) ----
    #pragma unroll
    for (int ks = 0; ks < 8; ks++) {
      uint4 pa0, pa1;
      ldsm4(pa0, PsB + pa_lane + (uint32_t)(((w * 32) * 68 + ks * 8) * 4));
      ldsm4(pa1, PsB + pa_lane + (uint32_t)(((w * 32 + 16) * 68 + ks * 8) * 4));
      #pragma unroll
      for (int nt = 0; nt < 8; nt++) {
        uint2 bv;
        bv.x = Vs[(8 * ks + tq) * 72 + 8 * nt + r0];
        bv.y = Vs[(8 * ks + tq + 4) * 72 + 8 * nt + r0];
        mma_tf32(o[0][nt], pa0, bv);
        mma_tf32(o[1][nt], pa1, bv);
      }
    }
  }

  // ---- epilogue: normalize, write [B,T,C] ----
  #pragma unroll
  for (int m = 0; m < 2; m++) {
    float inv0 = 1.0f / lrow[m][0], inv1 = 1.0f / lrow[m][1];
    float* orow0 = out + ((size_t)b * SEQ + q0 + w * 32 + m * 16 + r0) * EMBED + h * HDIM;
    float* orow1 = orow0 + (size_t)8 * EMBED;
    #pragma unroll
    for (int nt = 0; nt < 8; nt++) {
      *(float2*)(orow0 + 8 * nt + 2 * tq) =
          make_float2(o[m][nt][0] * inv0, o[m][nt][1] * inv0);
      *(float2*)(orow1 + 8 * nt + 2 * tq) =
          make_float2(o[m][nt][2] * inv1, o[m][nt][3] * inv1);
    }
  }
}

// ---------------------------------------------------------------------------
extern "C" void kernel_launch(void* const* d_in, const int* in_sizes, int n_in,
                              void* d_out, int out_size)
{
  (void)in_sizes; (void)n_in; (void)out_size;
  const float* x     = (const float*)d_in[0];
  const float* qkv_w = (const float*)d_in[1];
  const float* qkv_b = (const float*)d_in[2];
  const float* out_w = (const float*)d_in[3];
  const float* out_b = (const float*)d_in[4];
  float* y = (float*)d_out;

  float *qkv = nullptr, *att = nullptr;
  cudaGetSymbolAddress((void**)&qkv, g_qkv);
  cudaGetSymbolAddress((void**)&att, g_att);

  cudaFuncSetAttribute(gemm_cpa,
                       cudaFuncAttributeMaxDynamicSharedMemorySize, GSMEM_BYTES);
  cudaFuncSetAttribute(flash_tc,
                       cudaFuncAttributeMaxDynamicSharedMemorySize,
                       FTOT * (int)sizeof(uint32_t));

  // 1) QKV projection
  gemm_cpa<<<dim3(QKVF/128, MTOT/128), 128, GSMEM_BYTES>>>(
      x, qkv_w, qkv_b, qkv, MTOT, QKVF, EMBED);
  // 2) Causal flash attention
  flash_tc<<<dim3(SEQ/128, BATCH*NHEAD), 128, FTOT*(int)sizeof(uint32_t)>>>(qkv, att);
  // 3) Output projection
  gemm_cpa<<<dim3(EMBED/128, MTOT/128), 128, GSMEM_BYTES>>>(
      att, out_w, out_b, y, MTOT, EMBED, EMBED);
}

// round 10
// speedup vs baseline: 1.2132x; 1.2132x over previous
#include <cuda_runtime.h>
#include <cuda_fp16.h>
#include <cstdint>

#define EMBED 1024
#define NHEAD 16
#define HDIM  64
#define BATCH 4
#define SEQ   2048
#define MTOT  (BATCH*SEQ)      /* 8192 */
#define QKVF  (3*EMBED)        /* 3072 */

// Scratch (device globals: allocation-free per harness rules)
__device__ float g_qkv[(size_t)MTOT * QKVF];   // [M, 3C]
__device__ float g_att[(size_t)MTOT * EMBED];  // [M, C]

__device__ __forceinline__ uint32_t f2h2(float a, float b) {
  __half2 h = __floats2half2_rn(a, b);
  return *(uint32_t*)&h;
}

__device__ __forceinline__ void mma_f16(float c[4], const uint4& a, const uint2& b) {
  asm volatile(
    "mma.sync.aligned.m16n8k16.row.col.f32.f16.f16.f32 "
    "{%0,%1,%2,%3}, {%4,%5,%6,%7}, {%8,%9}, {%0,%1,%2,%3};\n"
    : "+f"(c[0]), "+f"(c[1]), "+f"(c[2]), "+f"(c[3])
    : "r"(a.x), "r"(a.y), "r"(a.z), "r"(a.w), "r"(b.x), "r"(b.y));
}

__device__ __forceinline__ uint32_t smem_u32(const void* p) {
  uint32_t a;
  asm("{ .reg .u64 t; cvta.to.shared.u64 t, %1; cvt.u32.u64 %0, t; }"
      : "=r"(a) : "l"(p));
  return a;
}

__device__ __forceinline__ void ldsm4(uint4& d, uint32_t addr) {
  asm volatile("ldmatrix.sync.aligned.m8n8.x4.shared.b16 {%0,%1,%2,%3}, [%4];"
               : "=r"(d.x), "=r"(d.y), "=r"(d.z), "=r"(d.w) : "r"(addr));
}

__device__ __forceinline__ void ldsm4t(uint4& d, uint32_t addr) {
  asm volatile("ldmatrix.sync.aligned.m8n8.x4.trans.shared.b16 {%0,%1,%2,%3}, [%4];"
               : "=r"(d.x), "=r"(d.y), "=r"(d.z), "=r"(d.w) : "r"(addr));
}

// ===========================================================================
// FP16 GEMM (fp32 accum): C[M,N] = A[M,K] @ B[N,K]^T + bias[N]
// CTA 128x128x32, 256 threads = 8 warps (4m x 2n), warp tile 32x64.
// R6's proven reg-prefetch ping-pong loop. fp16 tiles, rows padded to 80B
// (stride 20 words: ldsm rows hit banks 20r mod 32 - all distinct).
// a-frag: one ldmatrix.x4 per (mf, kstep); b-frag: one x4 per nt (both ksteps).
// ===========================================================================
#define GROWB 80
#define GATILE_B (128 * GROWB)          /* 10240 B */
#define GSTAGE_B (2 * GATILE_B)         /* 20480 B */
#define GSMEM_BYTES (2 * GSTAGE_B)      /* 40960 B */

__global__ __launch_bounds__(256, 2) void gemm_f16(
    const float* __restrict__ A, const float* __restrict__ Bm,
    const float* __restrict__ bias, float* __restrict__ C,
    int M, int N, int K)
{
  extern __shared__ char gsm[];
  const uint32_t sb = smem_u32(gsm);

  const int tid  = threadIdx.x;
  const int lane = tid & 31;
  const int wid  = tid >> 5;
  const int wm   = wid & 3;          // 32-row strip
  const int wn   = wid >> 2;         // 64-col strip
  const int m0   = blockIdx.y * 128;
  const int n0   = blockIdx.x * 128;
  const int r0   = lane >> 2;
  const int tq   = lane & 3;

  // ldmatrix lane offsets (bytes)
  const uint32_t a_lane = (uint32_t)((lane & 7) * GROWB +
                          ((lane >> 3) & 1) * 8 * GROWB + (lane >> 4) * 16);
  const uint32_t b_lane = (uint32_t)((lane & 7) * GROWB + (lane >> 3) * 16);

  float acc[2][8][4];
  #pragma unroll
  for (int i = 0; i < 2; i++)
    #pragma unroll
    for (int j = 0; j < 8; j++)
      #pragma unroll
      for (int r = 0; r < 4; r++) acc[i][j][r] = 0.0f;

  float4 va[4], vb[4];

  auto load_tiles = [&](int k0) {
    #pragma unroll
    for (int i = 0; i < 4; i++) {
      int idx = tid + 256 * i;           // 0..1023
      int row = idx >> 3, g = idx & 7;   // 8 float4 per 32-elem row
      va[i] = *(const float4*)(A  + (size_t)(m0 + row) * K + k0 + g * 4);
      vb[i] = *(const float4*)(Bm + (size_t)(n0 + row) * K + k0 + g * 4);
    }
  };

  auto store_tiles = [&](int s) {
    const uint32_t base = sb + (uint32_t)s * GSTAGE_B;
    #pragma unroll
    for (int i = 0; i < 4; i++) {
      int idx = tid + 256 * i;
      int row = idx >> 3, g = idx & 7;
      uint32_t off = (uint32_t)(row * GROWB + g * 8);
      uint2 au = make_uint2(f2h2(va[i].x, va[i].y), f2h2(va[i].z, va[i].w));
      uint2 bu = make_uint2(f2h2(vb[i].x, vb[i].y), f2h2(vb[i].z, vb[i].w));
      *(uint2*)(gsm + (base - sb) + off)            = au;
      *(uint2*)(gsm + (base - sb) + GATILE_B + off) = bu;
    }
  };

  auto compute = [&](int s) {
    const uint32_t As = sb + (uint32_t)s * GSTAGE_B + (uint32_t)(wm * 32 * GROWB);
    const uint32_t Bs = sb + (uint32_t)s * GSTAGE_B + GATILE_B +
                        (uint32_t)(wn * 64 * GROWB);
    uint4 af[2][2];   // [kstep][mf]
    #pragma unroll
    for (int ks = 0; ks < 2; ks++)
      #pragma unroll
      for (int mf = 0; mf < 2; mf++)
        ldsm4(af[ks][mf], As + a_lane + (uint32_t)(mf * 16 * GROWB + ks * 32));
    #pragma unroll
    for (int nt = 0; nt < 8; nt++) {
      uint4 braw;
      ldsm4(braw, Bs + b_lane + (uint32_t)(nt * 8 * GROWB));
      uint2 bf0 = make_uint2(braw.x, braw.y);   // k0-15
      uint2 bf1 = make_uint2(braw.z, braw.w);   // k16-31
      #pragma unroll
      for (int mf = 0; mf < 2; mf++) {
        mma_f16(acc[mf][nt], af[0][mf], bf0);
        mma_f16(acc[mf][nt], af[1][mf], bf1);
      }
    }
  };

  load_tiles(0);
  store_tiles(0);
  __syncthreads();

  const int nk = K >> 5;
  for (int t = 0; t < nk; t++) {
    if (t + 1 < nk) load_tiles((t + 1) << 5);
    compute(t & 1);
    if (t + 1 < nk) {
      __syncthreads();
      store_tiles((t + 1) & 1);
      __syncthreads();
    }
  }

  const int gn_base = n0 + wn * 64 + (tq << 1);
  #pragma unroll
  for (int mf = 0; mf < 2; mf++) {
    int gm = m0 + wm * 32 + mf * 16 + r0;
    #pragma unroll
    for (int nt = 0; nt < 8; nt++) {
      int gn = gn_base + nt * 8;
      float b0 = bias[gn], b1 = bias[gn + 1];
      float2 v0 = make_float2(acc[mf][nt][0] + b0, acc[mf][nt][1] + b1);
      float2 v1 = make_float2(acc[mf][nt][2] + b0, acc[mf][nt][3] + b1);
      *(float2*)(C + (size_t)gm * N + gn)       = v0;
      *(float2*)(C + (size_t)(gm + 8) * N + gn) = v1;
    }
  }
}

// ===========================================================================
// Flash attention, FP16 mma m16n8k16 (fp32 softmax + accum).
// 128 threads = 4 warps of 32q x 64k. fp16 tiles, 144B row stride
// (36 words: ldsm rows hit banks 4r - conflict-free).
// K b-frags: ldmatrix.x4; P a-frags: ldmatrix.x4; V b-frags: ldmatrix.x4.trans.
// ===========================================================================
#define FQF_B 0                       /* 8 frags x 4 ks x 128 words = 16384 B */
#define FKT_B 16384                   /* 64 x 144 = 9216 B */
#define FVS_B (16384 + 9216)          /* 9216 B */
#define FPS_B (16384 + 2*9216)        /* 128 x 144 = 18432 B */
#define FTOT_B (16384 + 2*9216 + 18432)  /* 53248 B */

__global__ __launch_bounds__(128) void flash_f16(
    const float* __restrict__ qkv, float* __restrict__ out)
{
  extern __shared__ char fsm[];
  uint32_t* QF = (uint32_t*)(fsm + FQF_B);
  const uint32_t sbase = smem_u32(fsm);
  const uint32_t KtB = sbase + FKT_B;
  const uint32_t VsB = sbase + FVS_B;
  const uint32_t PsB = sbase + FPS_B;

  const int tid  = threadIdx.x;
  const int lane = tid & 31;
  const int w    = tid >> 5;
  const int bx   = blockIdx.x;
  const int bh   = blockIdx.y;
  const int b    = bh >> 4;
  const int h    = bh & 15;
  const int q0   = bx * 128;

  const float* qbase = qkv + ((size_t)b * SEQ + q0) * QKVF + h * HDIM;
  const float* kbase = qkv + ((size_t)b * SEQ) * QKVF + EMBED + h * HDIM;
  const float* vbase = kbase + EMBED;

  // ---- Q scatter into fp16 fragment layout (once), scaled by 1/8 ----
  for (int e = tid; e < 128 * 16; e += 128) {
    int r = e >> 4, c4 = (e & 15) << 2;      // d = c4..c4+3
    float4 qv = *(const float4*)(qbase + (size_t)r * QKVF + c4);
    int wq = r >> 5, m = (r >> 4) & 1, rr = r & 15;
    int ks = c4 >> 4, kk = c4 & 15;
    int frag = ((wq * 2 + m) * 4 + ks);
    int ln0 = ((rr & 7) << 2) | ((kk & 7) >> 1);
    int rg  = (rr >> 3) | ((kk >> 3) << 1);
    QF[(frag * 128) + ln0 * 4 + rg]       = f2h2(qv.x * 0.125f, qv.y * 0.125f);
    QF[(frag * 128) + (ln0 + 1) * 4 + rg] = f2h2(qv.z * 0.125f, qv.w * 0.125f);
  }

  const int r0 = lane >> 2;
  const int tq = lane & 3;
  const int qmin = q0 + w * 32;
  const int qmax = qmin + 31;
  const int qg[2] = { qmin + r0, qmin + 16 + r0 };

  // ldmatrix lane offsets (bytes)
  const uint32_t kb_lane = (uint32_t)((lane & 7) * 144 + (lane >> 3) * 16);
  const uint32_t pa_lane = (uint32_t)((lane & 7) * 144 +
                           ((lane >> 3) & 1) * 8 * 144 + (lane >> 4) * 16);
  const int vm = lane >> 3;   // matrix index for trans V
  const uint32_t vb_lane = (uint32_t)(((vm & 1) * 8 + (lane & 7)) * 144 +
                                      (vm >> 1) * 16);

  float mrow[2][2], lrow[2][2];
  #pragma unroll
  for (int m = 0; m < 2; m++) {
    mrow[m][0] = mrow[m][1] = -1e30f;
    lrow[m][0] = lrow[m][1] = 0.0f;
  }
  float o[2][8][4];
  #pragma unroll
  for (int m = 0; m < 2; m++)
    #pragma unroll
    for (int nt = 0; nt < 8; nt++)
      #pragma unroll
      for (int j = 0; j < 4; j++) o[m][nt][j] = 0.0f;

  const int nkv = 2 * bx + 2;
  for (int kv = 0; kv < nkv; kv++) {
    const int k0 = kv * 64;
    __syncthreads();
    // ---- fill K/V fp16 tiles ----
    for (int e = tid; e < 64 * 16; e += 128) {
      int r = e >> 4, c4 = (e & 15) << 2;
      float4 kf4 = *(const float4*)(kbase + (size_t)(k0 + r) * QKVF + c4);
      float4 vf4 = *(const float4*)(vbase + (size_t)(k0 + r) * QKVF + c4);
      uint32_t off = (uint32_t)(r * 144 + c4 * 2);
      *(uint2*)(fsm + FKT_B + off) = make_uint2(f2h2(kf4.x, kf4.y), f2h2(kf4.z, kf4.w));
      *(uint2*)(fsm + FVS_B + off) = make_uint2(f2h2(vf4.x, vf4.y), f2h2(vf4.z, vf4.w));
    }
    __syncthreads();

    if (k0 > qmax) continue;

    // ---- Q a-frags (LDS.128 from fragment layout) ----
    uint4 qa[2][4];   // [m][ks]
    #pragma unroll
    for (int m = 0; m < 2; m++)
      #pragma unroll
      for (int ks = 0; ks < 4; ks++)
        qa[m][ks] = *(const uint4*)&QF[(((w * 2 + m) * 4 + ks) * 128) + lane * 4];

    // ---- S = Q @ K^T ----
    float s[2][8][4];
    #pragma unroll
    for (int m = 0; m < 2; m++)
      #pragma unroll
      for (int nt = 0; nt < 8; nt++)
        s[m][nt][0] = s[m][nt][1] = s[m][nt][2] = s[m][nt][3] = 0.0f;

    #pragma unroll
    for (int nt = 0; nt < 8; nt++) {
      uint4 kr0, kr1;
      ldsm4(kr0, KtB + kb_lane + (uint32_t)(nt * 8 * 144));        // d 0-31
      ldsm4(kr1, KtB + kb_lane + (uint32_t)(nt * 8 * 144 + 64));   // d 32-63
      uint2 bk[4] = { make_uint2(kr0.x, kr0.y), make_uint2(kr0.z, kr0.w),
                      make_uint2(kr1.x, kr1.y), make_uint2(kr1.z, kr1.w) };
      #pragma unroll
      for (int ks = 0; ks < 4; ks++) {
        mma_f16(s[0][nt], qa[0][ks], bk[ks]);
        mma_f16(s[1][nt], qa[1][ks], bk[ks]);
      }
    }

    // ---- causal mask ----
    if (k0 + 63 > qmin) {
      #pragma unroll
      for (int m = 0; m < 2; m++) {
        #pragma unroll
        for (int nt = 0; nt < 8; nt++) {
          int c0 = k0 + 8 * nt + 2 * tq;
          int c1 = c0 + 1;
          if (c0 > qg[m])     s[m][nt][0] = -1e30f;
          if (c1 > qg[m])     s[m][nt][1] = -1e30f;
          if (c0 > qg[m] + 8) s[m][nt][2] = -1e30f;
          if (c1 > qg[m] + 8) s[m][nt][3] = -1e30f;
        }
      }
    }

    // ---- online softmax per m-frag; P -> fp16 smem ----
    #pragma unroll
    for (int m = 0; m < 2; m++) {
      float mx0 = -1e30f, mx1 = -1e30f;
      #pragma unroll
      for (int nt = 0; nt < 8; nt++) {
        mx0 = fmaxf(mx0, fmaxf(s[m][nt][0], s[m][nt][1]));
        mx1 = fmaxf(mx1, fmaxf(s[m][nt][2], s[m][nt][3]));
      }
      mx0 = fmaxf(mx0, __shfl_xor_sync(0xffffffffu, mx0, 1));
      mx0 = fmaxf(mx0, __shfl_xor_sync(0xffffffffu, mx0, 2));
      mx1 = fmaxf(mx1, __shfl_xor_sync(0xffffffffu, mx1, 1));
      mx1 = fmaxf(mx1, __shfl_xor_sync(0xffffffffu, mx1, 2));

      float mn0 = fmaxf(mrow[m][0], mx0), mn1 = fmaxf(mrow[m][1], mx1);
      float a0 = __expf(mrow[m][0] - mn0), a1 = __expf(mrow[m][1] - mn1);
      mrow[m][0] = mn0; mrow[m][1] = mn1;

      const int prow = w * 32 + m * 16 + r0;
      float rs0 = 0.0f, rs1 = 0.0f;
      #pragma unroll
      for (int nt = 0; nt < 8; nt++) {
        float p0 = __expf(s[m][nt][0] - mn0);
        float p1 = __expf(s[m][nt][1] - mn0);
        float p2 = __expf(s[m][nt][2] - mn1);
        float p3 = __expf(s[m][nt][3] - mn1);
        rs0 += p0 + p1;
        rs1 += p2 + p3;
        *(uint32_t*)(fsm + FPS_B + prow * 144 + (8 * nt + 2 * tq) * 2) = f2h2(p0, p1);
        *(uint32_t*)(fsm + FPS_B + (prow + 8) * 144 + (8 * nt + 2 * tq) * 2) = f2h2(p2, p3);
      }
      rs0 += __shfl_xor_sync(0xffffffffu, rs0, 1);
      rs0 += __shfl_xor_sync(0xffffffffu, rs0, 2);
      rs1 += __shfl_xor_sync(0xffffffffu, rs1, 1);
      rs1 += __shfl_xor_sync(0xffffffffu, rs1, 2);
      lrow[m][0] = lrow[m][0] * a0 + rs0;
      lrow[m][1] = lrow[m][1] * a1 + rs1;
      #pragma unroll
      for (int nt = 0; nt < 8; nt++) {
        o[m][nt][0] *= a0; o[m][nt][1] *= a0;
        o[m][nt][2] *= a1; o[m][nt][3] *= a1;
      }
    }

    __syncwarp();   // Ps (per-warp rows) visible within warp

    // ---- O += P @ V ----
    #pragma unroll
    for (int ks = 0; ks < 4; ks++) {     // key 16-chunks
      uint4 pa0, pa1;
      ldsm4(pa0, PsB + pa_lane + (uint32_t)((w * 32) * 144 + ks * 32));
      ldsm4(pa1, PsB + pa_lane + (uint32_t)((w * 32 + 16) * 144 + ks * 32));
      #pragma unroll
      for (int j = 0; j < 4; j++) {      // nt pairs (2j, 2j+1)
        uint4 vr;
        ldsm4t(vr, VsB + vb_lane + (uint32_t)(16 * ks * 144 + j * 32));
        uint2 bv0 = make_uint2(vr.x, vr.y);   // nt=2j
        uint2 bv1 = make_uint2(vr.z, vr.w);   // nt=2j+1
        mma_f16(o[0][2*j],     pa0, bv0);
        mma_f16(o[0][2*j + 1], pa0, bv1);
        mma_f16(o[1][2*j],     pa1, bv0);
        mma_f16(o[1][2*j + 1], pa1, bv1);
      }
    }
  }

  // ---- epilogue: normalize, write [B,T,C] ----
  #pragma unroll
  for (int m = 0; m < 2; m++) {
    float inv0 = 1.0f / lrow[m][0], inv1 = 1.0f / lrow[m][1];
    float* orow0 = out + ((size_t)b * SEQ + q0 + w * 32 + m * 16 + r0) * EMBED + h * HDIM;
    float* orow1 = orow0 + (size_t)8 * EMBED;
    #pragma unroll
    for (int nt = 0; nt < 8; nt++) {
      *(float2*)(orow0 + 8 * nt + 2 * tq) =
          make_float2(o[m][nt][0] * inv0, o[m][nt][1] * inv0);
      *(float2*)(orow1 + 8 * nt + 2 * tq) =
          make_float2(o[m][nt][2] * inv1, o[m][nt][3] * inv1);
    }
  }
}

// ---------------------------------------------------------------------------
extern "C" void kernel_launch(void* const* d_in, const int* in_sizes, int n_in,
                              void* d_out, int out_size)
{
  (void)in_sizes; (void)n_in; (void)out_size;
  const float* x     = (const float*)d_in[0];
  const float* qkv_w = (const float*)d_in[1];
  const float* qkv_b = (const float*)d_in[2];
  const float* out_w = (const float*)d_in[3];
  const float* out_b = (const float*)d_in[4];
  float* y = (float*)d_out;

  float *qkv = nullptr, *att = nullptr;
  cudaGetSymbolAddress((void**)&qkv, g_qkv);
  cudaGetSymbolAddress((void**)&att, g_att);

  cudaFuncSetAttribute(gemm_f16,
                       cudaFuncAttributeMaxDynamicSharedMemorySize, GSMEM_BYTES);
  cudaFuncSetAttribute(flash_f16,
                       cudaFuncAttributeMaxDynamicSharedMemorySize, FTOT_B);

  // 1) QKV projection (fp16 mma, fp32 accum)
  gemm_f16<<<dim3(QKVF/128, MTOT/128), 256, GSMEM_BYTES>>>(
      x, qkv_w, qkv_b, qkv, MTOT, QKVF, EMBED);
  // 2) Causal flash attention (fp16 mma, fp32 softmax)
  flash_f16<<<dim3(SEQ/128, BATCH*NHEAD), 128, FTOT_B>>>(qkv, att);
  // 3) Output projection
  gemm_f16<<<dim3(EMBED/128, MTOT/128), 256, GSMEM_BYTES>>>(
      att, out_w, out_b, y, MTOT, EMBED, EMBED);
}

// round 11
// speedup vs baseline: 2.2652x; 1.8671x over previous
#include <cuda_runtime.h>
#include <cuda_fp16.h>
#include <cstdint>

#define EMBED 1024
#define NHEAD 16
#define HDIM  64
#define BATCH 4
#define SEQ   2048
#define MTOT  (BATCH*SEQ)      /* 8192 */
#define QKVF  (3*EMBED)        /* 3072 */

// fp16 scratch (device globals: allocation-free per harness rules)
__device__ __half g_hx[(size_t)MTOT * EMBED];     // x in fp16
__device__ __half g_hw_qkv[(size_t)QKVF * EMBED]; // qkv_w fp16
__device__ __half g_hw_out[(size_t)EMBED * EMBED];// out_w fp16
__device__ __half g_hqkv[(size_t)MTOT * QKVF];    // qkv activations fp16
__device__ __half g_hatt[(size_t)MTOT * EMBED];   // attention output fp16

__device__ __forceinline__ uint32_t f2h2(float a, float b) {
  __half2 h = __floats2half2_rn(a, b);
  return *(uint32_t*)&h;
}

__device__ __forceinline__ void mma_f16(float c[4], const uint4& a, const uint2& b) {
  asm volatile(
    "mma.sync.aligned.m16n8k16.row.col.f32.f16.f16.f32 "
    "{%0,%1,%2,%3}, {%4,%5,%6,%7}, {%8,%9}, {%0,%1,%2,%3};\n"
    : "+f"(c[0]), "+f"(c[1]), "+f"(c[2]), "+f"(c[3])
    : "r"(a.x), "r"(a.y), "r"(a.z), "r"(a.w), "r"(b.x), "r"(b.y));
}

__device__ __forceinline__ uint32_t smem_u32(const void* p) {
  uint32_t a;
  asm("{ .reg .u64 t; cvta.to.shared.u64 t, %1; cvt.u32.u64 %0, t; }"
      : "=r"(a) : "l"(p));
  return a;
}

__device__ __forceinline__ void ldsm4(uint4& d, uint32_t addr) {
  asm volatile("ldmatrix.sync.aligned.m8n8.x4.shared.b16 {%0,%1,%2,%3}, [%4];"
               : "=r"(d.x), "=r"(d.y), "=r"(d.z), "=r"(d.w) : "r"(addr));
}

__device__ __forceinline__ void ldsm4t(uint4& d, uint32_t addr) {
  asm volatile("ldmatrix.sync.aligned.m8n8.x4.trans.shared.b16 {%0,%1,%2,%3}, [%4];"
               : "=r"(d.x), "=r"(d.y), "=r"(d.z), "=r"(d.w) : "r"(addr));
}

__device__ __forceinline__ void cp16(uint32_t dst, const void* src) {
  asm volatile("cp.async.ca.shared.global [%0], [%1], 16;"
               :: "r"(dst), "l"(src) : "memory");
}
__device__ __forceinline__ void cpcommit() {
  asm volatile("cp.async.commit_group;" ::: "memory");
}
template<int N> __device__ __forceinline__ void cpwait() {
  asm volatile("cp.async.wait_group %0;" :: "n"(N) : "memory");
}

// ---------------------------------------------------------------------------
// fp32 -> fp16 conversion pass (vectorized)
// ---------------------------------------------------------------------------
__global__ void f2h_kernel(const float4* __restrict__ src, uint2* __restrict__ dst,
                           int n4)
{
  int i = blockIdx.x * blockDim.x + threadIdx.x;
  if (i < n4) {
    float4 v = src[i];
    dst[i] = make_uint2(f2h2(v.x, v.y), f2h2(v.z, v.w));
  }
}

// ===========================================================================
// FP16 GEMM (fp32 accum): C[M,N] = A[M,K] @ B[N,K]^T + bias[N]
// A, B fp16. CTA 128x128x32, 256 threads = 8 warps (4m x 2n), warp 32x64.
// 4-stage cp.async ring (81920 B smem), ldmatrix fragment loads.
// Rows padded to 80B: ldsm row bank-quads 5r mod 8 -> conflict-free.
// OUTH: store fp16 (intermediates) or fp32 (final output).
// ===========================================================================
#define GROWB 80
#define GATILE_B (128 * GROWB)          /* 10240 B */
#define GSTAGE_B (2 * GATILE_B)         /* 20480 B */
#define GSMEM_BYTES (4 * GSTAGE_B)      /* 81920 B */

template<bool OUTH>
__global__ __launch_bounds__(256, 2) void gemm_h(
    const __half* __restrict__ A, const __half* __restrict__ Bm,
    const float* __restrict__ bias, void* __restrict__ Cv,
    int M, int N, int K)
{
  extern __shared__ char gsm[];
  const uint32_t sb = smem_u32(gsm);

  const int tid  = threadIdx.x;
  const int lane = tid & 31;
  const int wid  = tid >> 5;
  const int wm   = wid & 3;          // 32-row strip
  const int wn   = wid >> 2;         // 64-col strip
  const int m0   = blockIdx.y * 128;
  const int n0   = blockIdx.x * 128;
  const int r0   = lane >> 2;
  const int tq   = lane & 3;

  const uint32_t a_lane = (uint32_t)((lane & 7) * GROWB +
                          ((lane >> 3) & 1) * 8 * GROWB + (lane >> 4) * 16);
  const uint32_t b_lane = (uint32_t)((lane & 7) * GROWB + (lane >> 3) * 16);

  float acc[2][8][4];
  #pragma unroll
  for (int i = 0; i < 2; i++)
    #pragma unroll
    for (int j = 0; j < 8; j++)
      #pragma unroll
      for (int r = 0; r < 4; r++) acc[i][j][r] = 0.0f;

  // fill one stage: A 128x32 fp16 + B 128x32 fp16, 4 x 16B chunks per row
  auto fill = [&](int s, int k0) {
    const uint32_t base = sb + (uint32_t)s * GSTAGE_B;
    #pragma unroll
    for (int i = 0; i < 2; i++) {
      int idx = tid + 256 * i;          // 0..511
      int row = idx >> 2, ch = idx & 3;
      uint32_t off = (uint32_t)(row * GROWB + ch * 16);
      cp16(base + off,            A  + (size_t)(m0 + row) * K + k0 + ch * 8);
      cp16(base + GATILE_B + off, Bm + (size_t)(n0 + row) * K + k0 + ch * 8);
    }
    cpcommit();
  };

  auto compute = [&](int s) {
    const uint32_t As = sb + (uint32_t)s * GSTAGE_B + (uint32_t)(wm * 32 * GROWB);
    const uint32_t Bs = sb + (uint32_t)s * GSTAGE_B + GATILE_B +
                        (uint32_t)(wn * 64 * GROWB);
    uint4 af[2][2];   // [kstep][mf]
    #pragma unroll
    for (int ks = 0; ks < 2; ks++)
      #pragma unroll
      for (int mf = 0; mf < 2; mf++)
        ldsm4(af[ks][mf], As + a_lane + (uint32_t)(mf * 16 * GROWB + ks * 32));
    #pragma unroll
    for (int nt = 0; nt < 8; nt++) {
      uint4 braw;
      ldsm4(braw, Bs + b_lane + (uint32_t)(nt * 8 * GROWB));
      uint2 bf0 = make_uint2(braw.x, braw.y);
      uint2 bf1 = make_uint2(braw.z, braw.w);
      #pragma unroll
      for (int mf = 0; mf < 2; mf++) {
        mma_f16(acc[mf][nt], af[0][mf], bf0);
        mma_f16(acc[mf][nt], af[1][mf], bf1);
      }
    }
  };

  const int nk = K >> 5;   // >= 32 here
  fill(0, 0);
  fill(1, 32);
  fill(2, 64);

  for (int t = 0; t < nk; t++) {
    cpwait<2>();
    __syncthreads();
    if (t + 3 < nk) fill((t + 3) & 3, (t + 3) << 5);
    compute(t & 3);
  }

  // ---- epilogue ----
  const int gn_base = n0 + wn * 64 + (tq << 1);
  #pragma unroll
  for (int mf = 0; mf < 2; mf++) {
    int gm = m0 + wm * 32 + mf * 16 + r0;
    #pragma unroll
    for (int nt = 0; nt < 8; nt++) {
      int gn = gn_base + nt * 8;
      float b0 = bias[gn], b1 = bias[gn + 1];
      float c00 = acc[mf][nt][0] + b0, c01 = acc[mf][nt][1] + b1;
      float c10 = acc[mf][nt][2] + b0, c11 = acc[mf][nt][3] + b1;
      if (OUTH) {
        __half* C = (__half*)Cv;
        *(uint32_t*)(C + (size_t)gm * N + gn)       = f2h2(c00, c01);
        *(uint32_t*)(C + (size_t)(gm + 8) * N + gn) = f2h2(c10, c11);
      } else {
        float* C = (float*)Cv;
        *(float2*)(C + (size_t)gm * N + gn)       = make_float2(c00, c01);
        *(float2*)(C + (size_t)(gm + 8) * N + gn) = make_float2(c10, c11);
      }
    }
  }
}

// ===========================================================================
// Flash attention, FP16 mma m16n8k16 (fp32 softmax + accum), fp16 I/O.
// 128 threads = 4 warps of 32q x 64k. cp.async double-buffered K/V tiles.
// 144B row stride (bank-quads 9r mod 8 = r -> conflict-free ldsm).
// ===========================================================================
#define FQF_B  0                       /* 16384 B */
#define FKT0_B 16384                   /* K buf0: 64*144 = 9216 */
#define FVS0_B (16384 + 9216)
#define FKT1_B (16384 + 2*9216)
#define FVS1_B (16384 + 3*9216)
#define FPS_B  (16384 + 4*9216)        /* 128*144 = 18432 */
#define FTOT_B (16384 + 4*9216 + 18432)   /* 71680 B */

__global__ __launch_bounds__(128) void flash_h(
    const __half* __restrict__ qkv, __half* __restrict__ out)
{
  extern __shared__ char fsm[];
  uint32_t* QF = (uint32_t*)(fsm + FQF_B);
  const uint32_t sbase = smem_u32(fsm);
  const uint32_t KtB[2] = { sbase + FKT0_B, sbase + FKT1_B };
  const uint32_t VsB[2] = { sbase + FVS0_B, sbase + FVS1_B };
  const uint32_t PsB = sbase + FPS_B;

  const int tid  = threadIdx.x;
  const int lane = tid & 31;
  const int w    = tid >> 5;
  const int bx   = blockIdx.x;
  const int bh   = blockIdx.y;
  const int b    = bh >> 4;
  const int h    = bh & 15;
  const int q0   = bx * 128;

  const __half* qb = qkv + ((size_t)b * SEQ + q0) * QKVF + h * HDIM;
  const __half* kb = qkv + ((size_t)b * SEQ) * QKVF + EMBED + h * HDIM;
  const __half* vb = kb + EMBED;

  // ---- prefetch K/V tile 0 ----
  auto fillkv = [&](int buf, int k0) {
    #pragma unroll
    for (int i = 0; i < 4; i++) {
      int idx = tid + 128 * i;          // 0..511
      int row = idx >> 3, ch = idx & 7;
      uint32_t off = (uint32_t)(row * 144 + ch * 16);
      cp16(KtB[buf] + off, kb + (size_t)(k0 + row) * QKVF + ch * 8);
      cp16(VsB[buf] + off, vb + (size_t)(k0 + row) * QKVF + ch * 8);
    }
    cpcommit();
  };
  fillkv(0, 0);

  // ---- Q scatter into fp16 fragment layout (once), scaled by 1/8 ----
  {
    const __half2 sc = __floats2half2_rn(0.125f, 0.125f);
    for (int e = tid; e < 128 * 8; e += 128) {
      int r = e >> 3, c8 = (e & 7) << 3;
      uint4 qv = *(const uint4*)(qb + (size_t)r * QKVF + c8);
      uint32_t wds[4] = { qv.x, qv.y, qv.z, qv.w };
      int wq = r >> 5, m = (r >> 4) & 1, rr = r & 15;
      int frag = (wq * 2 + m) * 4 + (c8 >> 4);
      int rg = (rr >> 3) | (((c8 & 15) >> 3) << 1);
      #pragma unroll
      for (int j = 0; j < 4; j++) {
        __half2 hv = __hmul2(*(__half2*)&wds[j], sc);
        QF[frag * 128 + ((rr & 7) * 4 + j) * 4 + rg] = *(uint32_t*)&hv;
      }
    }
  }

  const int r0 = lane >> 2;
  const int tq = lane & 3;
  const int qmin = q0 + w * 32;
  const int qmax = qmin + 31;
  const int qg[2] = { qmin + r0, qmin + 16 + r0 };

  const uint32_t kb_lane = (uint32_t)((lane & 7) * 144 + (lane >> 3) * 16);
  const uint32_t pa_lane = (uint32_t)((lane & 7) * 144 +
                           ((lane >> 3) & 1) * 8 * 144 + (lane >> 4) * 16);
  const int vm = lane >> 3;
  const uint32_t vb_lane = (uint32_t)(((vm & 1) * 8 + (lane & 7)) * 144 +
                                      (vm >> 1) * 16);

  float mrow[2][2], lrow[2][2];
  #pragma unroll
  for (int m = 0; m < 2; m++) {
    mrow[m][0] = mrow[m][1] = -1e30f;
    lrow[m][0] = lrow[m][1] = 0.0f;
  }
  float o[2][8][4];
  #pragma unroll
  for (int m = 0; m < 2; m++)
    #pragma unroll
    for (int nt = 0; nt < 8; nt++)
      #pragma unroll
      for (int j = 0; j < 4; j++) o[m][nt][j] = 0.0f;

  const int nkv = 2 * bx + 2;
  for (int kv = 0; kv < nkv; kv++) {
    const int k0 = kv * 64;
    const int buf = kv & 1;
    __syncthreads();   // all warps done reading buf^1 (written next)
    if (kv + 1 < nkv) fillkv(buf ^ 1, k0 + 64);
    if (kv + 1 < nkv) cpwait<1>(); else cpwait<0>();
    __syncthreads();

    if (k0 > qmax) continue;

    // ---- Q a-frags ----
    uint4 qa[2][4];
    #pragma unroll
    for (int m = 0; m < 2; m++)
      #pragma unroll
      for (int ks = 0; ks < 4; ks++)
        qa[m][ks] = *(const uint4*)&QF[(((w * 2 + m) * 4 + ks) * 128) + lane * 4];

    // ---- S = Q @ K^T ----
    float s[2][8][4];
    #pragma unroll
    for (int m = 0; m < 2; m++)
      #pragma unroll
      for (int nt = 0; nt < 8; nt++)
        s[m][nt][0] = s[m][nt][1] = s[m][nt][2] = s[m][nt][3] = 0.0f;

    #pragma unroll
    for (int nt = 0; nt < 8; nt++) {
      uint4 kr0, kr1;
      ldsm4(kr0, KtB[buf] + kb_lane + (uint32_t)(nt * 8 * 144));
      ldsm4(kr1, KtB[buf] + kb_lane + (uint32_t)(nt * 8 * 144 + 64));
      uint2 bk[4] = { make_uint2(kr0.x, kr0.y), make_uint2(kr0.z, kr0.w),
                      make_uint2(kr1.x, kr1.y), make_uint2(kr1.z, kr1.w) };
      #pragma unroll
      for (int ks = 0; ks < 4; ks++) {
        mma_f16(s[0][nt], qa[0][ks], bk[ks]);
        mma_f16(s[1][nt], qa[1][ks], bk[ks]);
      }
    }

    // ---- causal mask ----
    if (k0 + 63 > qmin) {
      #pragma unroll
      for (int m = 0; m < 2; m++) {
        #pragma unroll
        for (int nt = 0; nt < 8; nt++) {
          int c0 = k0 + 8 * nt + 2 * tq;
          int c1 = c0 + 1;
          if (c0 > qg[m])     s[m][nt][0] = -1e30f;
          if (c1 > qg[m])     s[m][nt][1] = -1e30f;
          if (c0 > qg[m] + 8) s[m][nt][2] = -1e30f;
          if (c1 > qg[m] + 8) s[m][nt][3] = -1e30f;
        }
      }
    }

    // ---- online softmax; P -> fp16 smem ----
    #pragma unroll
    for (int m = 0; m < 2; m++) {
      float mx0 = -1e30f, mx1 = -1e30f;
      #pragma unroll
      for (int nt = 0; nt < 8; nt++) {
        mx0 = fmaxf(mx0, fmaxf(s[m][nt][0], s[m][nt][1]));
        mx1 = fmaxf(mx1, fmaxf(s[m][nt][2], s[m][nt][3]));
      }
      mx0 = fmaxf(mx0, __shfl_xor_sync(0xffffffffu, mx0, 1));
      mx0 = fmaxf(mx0, __shfl_xor_sync(0xffffffffu, mx0, 2));
      mx1 = fmaxf(mx1, __shfl_xor_sync(0xffffffffu, mx1, 1));
      mx1 = fmaxf(mx1, __shfl_xor_sync(0xffffffffu, mx1, 2));

      float mn0 = fmaxf(mrow[m][0], mx0), mn1 = fmaxf(mrow[m][1], mx1);
      float a0 = __expf(mrow[m][0] - mn0), a1 = __expf(mrow[m][1] - mn1);
      mrow[m][0] = mn0; mrow[m][1] = mn1;

      const int prow = w * 32 + m * 16 + r0;
      float rs0 = 0.0f, rs1 = 0.0f;
      #pragma unroll
      for (int nt = 0; nt < 8; nt++) {
        float p0 = __expf(s[m][nt][0] - mn0);
        float p1 = __expf(s[m][nt][1] - mn0);
        float p2 = __expf(s[m][nt][2] - mn1);
        float p3 = __expf(s[m][nt][3] - mn1);
        rs0 += p0 + p1;
        rs1 += p2 + p3;
        *(uint32_t*)(fsm + FPS_B + prow * 144 + (8 * nt + 2 * tq) * 2) = f2h2(p0, p1);
        *(uint32_t*)(fsm + FPS_B + (prow + 8) * 144 + (8 * nt + 2 * tq) * 2) = f2h2(p2, p3);
      }
      rs0 += __shfl_xor_sync(0xffffffffu, rs0, 1);
      rs0 += __shfl_xor_sync(0xffffffffu, rs0, 2);
      rs1 += __shfl_xor_sync(0xffffffffu, rs1, 1);
      rs1 += __shfl_xor_sync(0xffffffffu, rs1, 2);
      lrow[m][0] = lrow[m][0] * a0 + rs0;
      lrow[m][1] = lrow[m][1] * a1 + rs1;
      #pragma unroll
      for (int nt = 0; nt < 8; nt++) {
        o[m][nt][0] *= a0; o[m][nt][1] *= a0;
        o[m][nt][2] *= a1; o[m][nt][3] *= a1;
      }
    }

    __syncwarp();

    // ---- O += P @ V ----
    #pragma unroll
    for (int ks = 0; ks < 4; ks++) {
      uint4 pa0, pa1;
      ldsm4(pa0, PsB + pa_lane + (uint32_t)((w * 32) * 144 + ks * 32));
      ldsm4(pa1, PsB + pa_lane + (uint32_t)((w * 32 + 16) * 144 + ks * 32));
      #pragma unroll
      for (int j = 0; j < 4; j++) {
        uint4 vr;
        ldsm4t(vr, VsB[buf] + vb_lane + (uint32_t)(16 * ks * 144 + j * 32));
        uint2 bv0 = make_uint2(vr.x, vr.y);
        uint2 bv1 = make_uint2(vr.z, vr.w);
        mma_f16(o[0][2*j],     pa0, bv0);
        mma_f16(o[0][2*j + 1], pa0, bv1);
        mma_f16(o[1][2*j],     pa1, bv0);
        mma_f16(o[1][2*j + 1], pa1, bv1);
      }
    }
  }

  // ---- epilogue: normalize, write fp16 [B,T,C] ----
  #pragma unroll
  for (int m = 0; m < 2; m++) {
    float inv0 = 1.0f / lrow[m][0], inv1 = 1.0f / lrow[m][1];
    __half* orow0 = out + ((size_t)b * SEQ + q0 + w * 32 + m * 16 + r0) * EMBED + h * HDIM;
    __half* orow1 = orow0 + (size_t)8 * EMBED;
    #pragma unroll
    for (int nt = 0; nt < 8; nt++) {
      *(uint32_t*)(orow0 + 8 * nt + 2 * tq) =
          f2h2(o[m][nt][0] * inv0, o[m][nt][1] * inv0);
      *(uint32_t*)(orow1 + 8 * nt + 2 * tq) =
          f2h2(o[m][nt][2] * inv1, o[m][nt][3] * inv1);
    }
  }
}

// ---------------------------------------------------------------------------
extern "C" void kernel_launch(void* const* d_in, const int* in_sizes, int n_in,
                              void* d_out, int out_size)
{
  (void)in_sizes; (void)n_in; (void)out_size;
  const float* x     = (const float*)d_in[0];
  const float* qkv_w = (const float*)d_in[1];
  const float* qkv_b = (const float*)d_in[2];
  const float* out_w = (const float*)d_in[3];
  const float* out_b = (const float*)d_in[4];
  float* y = (float*)d_out;

  __half *hx, *hwq, *hwo, *hqkv, *hatt;
  cudaGetSymbolAddress((void**)&hx,   g_hx);
  cudaGetSymbolAddress((void**)&hwq,  g_hw_qkv);
  cudaGetSymbolAddress((void**)&hwo,  g_hw_out);
  cudaGetSymbolAddress((void**)&hqkv, g_hqkv);
  cudaGetSymbolAddress((void**)&hatt, g_hatt);

  cudaFuncSetAttribute(gemm_h<true>,
                       cudaFuncAttributeMaxDynamicSharedMemorySize, GSMEM_BYTES);
  cudaFuncSetAttribute(gemm_h<false>,
                       cudaFuncAttributeMaxDynamicSharedMemorySize, GSMEM_BYTES);
  cudaFuncSetAttribute(flash_h,
                       cudaFuncAttributeMaxDynamicSharedMemorySize, FTOT_B);

  // 0) fp32 -> fp16 conversions
  {
    int n4x = MTOT * EMBED / 4;
    f2h_kernel<<<(n4x + 255) / 256, 256>>>((const float4*)x, (uint2*)hx, n4x);
    int n4q = QKVF * EMBED / 4;
    f2h_kernel<<<(n4q + 255) / 256, 256>>>((const float4*)qkv_w, (uint2*)hwq, n4q);
    int n4o = EMBED * EMBED / 4;
    f2h_kernel<<<(n4o + 255) / 256, 256>>>((const float4*)out_w, (uint2*)hwo, n4o);
  }

  // 1) QKV projection (fp16 in, fp16 out)
  gemm_h<true><<<dim3(QKVF/128, MTOT/128), 256, GSMEM_BYTES>>>(
      hx, hwq, qkv_b, hqkv, MTOT, QKVF, EMBED);
  // 2) Causal flash attention (fp16 I/O, fp32 softmax)
  flash_h<<<dim3(SEQ/128, BATCH*NHEAD), 128, FTOT_B>>>(hqkv, hatt);
  // 3) Output projection (fp16 in, fp32 out)
  gemm_h<false><<<dim3(EMBED/128, MTOT/128), 256, GSMEM_BYTES>>>(
      hatt, hwo, out_b, y, MTOT, EMBED, EMBED);
}

// round 12
// speedup vs baseline: 2.4566x; 1.0845x over previous
#include <cuda_runtime.h>
#include <cuda_fp16.h>
#include <cstdint>

#define EMBED 1024
#define NHEAD 16
#define HDIM  64
#define BATCH 4
#define SEQ   2048
#define MTOT  (BATCH*SEQ)      /* 8192 */
#define QKVF  (3*EMBED)        /* 3072 */

// fp16 scratch (device globals: allocation-free per harness rules)
__device__ __half g_hx[(size_t)MTOT * EMBED];     // x in fp16
__device__ __half g_hw_qkv[(size_t)QKVF * EMBED]; // qkv_w fp16
__device__ __half g_hw_out[(size_t)EMBED * EMBED];// out_w fp16
__device__ __half g_hqkv[(size_t)MTOT * QKVF];    // qkv activations fp16
__device__ __half g_hatt[(size_t)MTOT * EMBED];   // attention output fp16

__device__ __forceinline__ uint32_t f2h2(float a, float b) {
  __half2 h = __floats2half2_rn(a, b);
  return *(uint32_t*)&h;
}

__device__ __forceinline__ void mma_f16(float c[4], const uint4& a, const uint2& b) {
  asm volatile(
    "mma.sync.aligned.m16n8k16.row.col.f32.f16.f16.f32 "
    "{%0,%1,%2,%3}, {%4,%5,%6,%7}, {%8,%9}, {%0,%1,%2,%3};\n"
    : "+f"(c[0]), "+f"(c[1]), "+f"(c[2]), "+f"(c[3])
    : "r"(a.x), "r"(a.y), "r"(a.z), "r"(a.w), "r"(b.x), "r"(b.y));
}

__device__ __forceinline__ uint32_t smem_u32(const void* p) {
  uint32_t a;
  asm("{ .reg .u64 t; cvta.to.shared.u64 t, %1; cvt.u32.u64 %0, t; }"
      : "=r"(a) : "l"(p));
  return a;
}

__device__ __forceinline__ void ldsm4(uint4& d, uint32_t addr) {
  asm volatile("ldmatrix.sync.aligned.m8n8.x4.shared.b16 {%0,%1,%2,%3}, [%4];"
               : "=r"(d.x), "=r"(d.y), "=r"(d.z), "=r"(d.w) : "r"(addr));
}

__device__ __forceinline__ void ldsm4t(uint4& d, uint32_t addr) {
  asm volatile("ldmatrix.sync.aligned.m8n8.x4.trans.shared.b16 {%0,%1,%2,%3}, [%4];"
               : "=r"(d.x), "=r"(d.y), "=r"(d.z), "=r"(d.w) : "r"(addr));
}

__device__ __forceinline__ void cp16(uint32_t dst, const void* src) {
  asm volatile("cp.async.ca.shared.global [%0], [%1], 16;"
               :: "r"(dst), "l"(src) : "memory");
}
__device__ __forceinline__ void cpcommit() {
  asm volatile("cp.async.commit_group;" ::: "memory");
}
template<int N> __device__ __forceinline__ void cpwait() {
  asm volatile("cp.async.wait_group %0;" :: "n"(N) : "memory");
}

// ---------------------------------------------------------------------------
// fp32 -> fp16 conversion pass (vectorized)
// ---------------------------------------------------------------------------
__global__ void f2h_kernel(const float4* __restrict__ src, uint2* __restrict__ dst,
                           int n4)
{
  int i = blockIdx.x * blockDim.x + threadIdx.x;
  if (i < n4) {
    float4 v = src[i];
    dst[i] = make_uint2(f2h2(v.x, v.y), f2h2(v.z, v.w));
  }
}

// ===========================================================================
// FP16 GEMM (fp32 accum): C[M,N] = A[M,K] @ B[N,K]^T + bias[N]
// CTA 128x128x32, 128 threads = 4 warps of 64x64 warp tiles (2m x 2n).
// Per chunk each warp: 8 a-ldsm.x4 + 8 b-ldsm.x4 -> 64 mma (max reuse/wf).
// 4-stage cp.async ring. Rows padded to 80B (bank-quads 5r mod 8: clean).
// ===========================================================================
#define GROWB 80
#define GATILE_B (128 * GROWB)          /* 10240 B */
#define GSTAGE_B (2 * GATILE_B)         /* 20480 B */
#define GSMEM_BYTES (4 * GSTAGE_B)      /* 81920 B */

template<bool OUTH>
__global__ __launch_bounds__(128, 2) void gemm_h(
    const __half* __restrict__ A, const __half* __restrict__ Bm,
    const float* __restrict__ bias, void* __restrict__ Cv,
    int M, int N, int K)
{
  extern __shared__ char gsm[];
  const uint32_t sb = smem_u32(gsm);

  const int tid  = threadIdx.x;
  const int lane = tid & 31;
  const int wid  = tid >> 5;
  const int wm   = wid & 1;          // 64-row strip
  const int wn   = wid >> 1;         // 64-col strip
  const int m0   = blockIdx.y * 128;
  const int n0   = blockIdx.x * 128;
  const int r0   = lane >> 2;
  const int tq   = lane & 3;

  const uint32_t a_lane = (uint32_t)((lane & 7) * GROWB +
                          ((lane >> 3) & 1) * 8 * GROWB + (lane >> 4) * 16);
  const uint32_t b_lane = (uint32_t)((lane & 7) * GROWB + (lane >> 3) * 16);

  float acc[4][8][4];
  #pragma unroll
  for (int i = 0; i < 4; i++)
    #pragma unroll
    for (int j = 0; j < 8; j++)
      #pragma unroll
      for (int r = 0; r < 4; r++) acc[i][j][r] = 0.0f;

  // fill one stage: A 128x32 fp16 + B 128x32 fp16 (4 x 16B chunks per row)
  auto fill = [&](int s, int k0) {
    const uint32_t base = sb + (uint32_t)s * GSTAGE_B;
    #pragma unroll
    for (int i = 0; i < 4; i++) {
      int idx = tid + 128 * i;          // 0..511
      int row = idx >> 2, ch = idx & 3;
      uint32_t off = (uint32_t)(row * GROWB + ch * 16);
      cp16(base + off,            A  + (size_t)(m0 + row) * K + k0 + ch * 8);
      cp16(base + GATILE_B + off, Bm + (size_t)(n0 + row) * K + k0 + ch * 8);
    }
    cpcommit();
  };

  auto compute = [&](int s) {
    const uint32_t As = sb + (uint32_t)s * GSTAGE_B + (uint32_t)(wm * 64 * GROWB);
    const uint32_t Bs = sb + (uint32_t)s * GSTAGE_B + GATILE_B +
                        (uint32_t)(wn * 64 * GROWB);
    uint4 af[2][4];   // [kstep][mf]
    #pragma unroll
    for (int mf = 0; mf < 4; mf++) {
      uint4 t0, t1;
      ldsm4(t0, As + a_lane + (uint32_t)(mf * 16 * GROWB));
      ldsm4(t1, As + a_lane + (uint32_t)(mf * 16 * GROWB + 32));
      af[0][mf] = t0;
      af[1][mf] = t1;
    }
    #pragma unroll
    for (int nt = 0; nt < 8; nt++) {
      uint4 braw;
      ldsm4(braw, Bs + b_lane + (uint32_t)(nt * 8 * GROWB));
      uint2 bf0 = make_uint2(braw.x, braw.y);   // k0-15
      uint2 bf1 = make_uint2(braw.z, braw.w);   // k16-31
      #pragma unroll
      for (int mf = 0; mf < 4; mf++) {
        mma_f16(acc[mf][nt], af[0][mf], bf0);
        mma_f16(acc[mf][nt], af[1][mf], bf1);
      }
    }
  };

  const int nk = K >> 5;   // >= 32 here
  fill(0, 0);
  fill(1, 32);
  fill(2, 64);

  for (int t = 0; t < nk; t++) {
    cpwait<2>();
    __syncthreads();
    if (t + 3 < nk) fill((t + 3) & 3, (t + 3) << 5);
    compute(t & 3);
  }

  // ---- epilogue ----
  const int gn_base = n0 + wn * 64 + (tq << 1);
  #pragma unroll
  for (int mf = 0; mf < 4; mf++) {
    int gm = m0 + wm * 64 + mf * 16 + r0;
    #pragma unroll
    for (int nt = 0; nt < 8; nt++) {
      int gn = gn_base + nt * 8;
      float b0 = bias[gn], b1 = bias[gn + 1];
      float c00 = acc[mf][nt][0] + b0, c01 = acc[mf][nt][1] + b1;
      float c10 = acc[mf][nt][2] + b0, c11 = acc[mf][nt][3] + b1;
      if (OUTH) {
        __half* C = (__half*)Cv;
        *(uint32_t*)(C + (size_t)gm * N + gn)       = f2h2(c00, c01);
        *(uint32_t*)(C + (size_t)(gm + 8) * N + gn) = f2h2(c10, c11);
      } else {
        float* C = (float*)Cv;
        *(float2*)(C + (size_t)gm * N + gn)       = make_float2(c00, c01);
        *(float2*)(C + (size_t)(gm + 8) * N + gn) = make_float2(c10, c11);
      }
    }
  }
}

// ===========================================================================
// Flash attention, FP16 mma m16n8k16 (fp32 softmax + accum), fp16 I/O.
// 128 threads = 4 warps of 32q x 64k. cp.async double-buffered K/V tiles.
// (unchanged from R11)
// ===========================================================================
#define FQF_B  0                       /* 16384 B */
#define FKT0_B 16384
#define FVS0_B (16384 + 9216)
#define FKT1_B (16384 + 2*9216)
#define FVS1_B (16384 + 3*9216)
#define FPS_B  (16384 + 4*9216)
#define FTOT_B (16384 + 4*9216 + 18432)   /* 71680 B */

__global__ __launch_bounds__(128) void flash_h(
    const __half* __restrict__ qkv, __half* __restrict__ out)
{
  extern __shared__ char fsm[];
  uint32_t* QF = (uint32_t*)(fsm + FQF_B);
  const uint32_t sbase = smem_u32(fsm);
  const uint32_t KtB[2] = { sbase + FKT0_B, sbase + FKT1_B };
  const uint32_t VsB[2] = { sbase + FVS0_B, sbase + FVS1_B };
  const uint32_t PsB = sbase + FPS_B;

  const int tid  = threadIdx.x;
  const int lane = tid & 31;
  const int w    = tid >> 5;
  const int bx   = blockIdx.x;
  const int bh   = blockIdx.y;
  const int b    = bh >> 4;
  const int h    = bh & 15;
  const int q0   = bx * 128;

  const __half* qb = qkv + ((size_t)b * SEQ + q0) * QKVF + h * HDIM;
  const __half* kb = qkv + ((size_t)b * SEQ) * QKVF + EMBED + h * HDIM;
  const __half* vb = kb + EMBED;

  auto fillkv = [&](int buf, int k0) {
    #pragma unroll
    for (int i = 0; i < 4; i++) {
      int idx = tid + 128 * i;
      int row = idx >> 3, ch = idx & 7;
      uint32_t off = (uint32_t)(row * 144 + ch * 16);
      cp16(KtB[buf] + off, kb + (size_t)(k0 + row) * QKVF + ch * 8);
      cp16(VsB[buf] + off, vb + (size_t)(k0 + row) * QKVF + ch * 8);
    }
    cpcommit();
  };
  fillkv(0, 0);

  {
    const __half2 sc = __floats2half2_rn(0.125f, 0.125f);
    for (int e = tid; e < 128 * 8; e += 128) {
      int r = e >> 3, c8 = (e & 7) << 3;
      uint4 qv = *(const uint4*)(qb + (size_t)r * QKVF + c8);
      uint32_t wds[4] = { qv.x, qv.y, qv.z, qv.w };
      int wq = r >> 5, m = (r >> 4) & 1, rr = r & 15;
      int frag = (wq * 2 + m) * 4 + (c8 >> 4);
      int rg = (rr >> 3) | (((c8 & 15) >> 3) << 1);
      #pragma unroll
      for (int j = 0; j < 4; j++) {
        __half2 hv = __hmul2(*(__half2*)&wds[j], sc);
        QF[frag * 128 + ((rr & 7) * 4 + j) * 4 + rg] = *(uint32_t*)&hv;
      }
    }
  }

  const int r0 = lane >> 2;
  const int tq = lane & 3;
  const int qmin = q0 + w * 32;
  const int qmax = qmin + 31;
  const int qg[2] = { qmin + r0, qmin + 16 + r0 };

  const uint32_t kb_lane = (uint32_t)((lane & 7) * 144 + (lane >> 3) * 16);
  const uint32_t pa_lane = (uint32_t)((lane & 7) * 144 +
                           ((lane >> 3) & 1) * 8 * 144 + (lane >> 4) * 16);
  const int vm = lane >> 3;
  const uint32_t vb_lane = (uint32_t)(((vm & 1) * 8 + (lane & 7)) * 144 +
                                      (vm >> 1) * 16);

  float mrow[2][2], lrow[2][2];
  #pragma unroll
  for (int m = 0; m < 2; m++) {
    mrow[m][0] = mrow[m][1] = -1e30f;
    lrow[m][0] = lrow[m][1] = 0.0f;
  }
  float o[2][8][4];
  #pragma unroll
  for (int m = 0; m < 2; m++)
    #pragma unroll
    for (int nt = 0; nt < 8; nt++)
      #pragma unroll
      for (int j = 0; j < 4; j++) o[m][nt][j] = 0.0f;

  const int nkv = 2 * bx + 2;
  for (int kv = 0; kv < nkv; kv++) {
    const int k0 = kv * 64;
    const int buf = kv & 1;
    __syncthreads();
    if (kv + 1 < nkv) fillkv(buf ^ 1, k0 + 64);
    if (kv + 1 < nkv) cpwait<1>(); else cpwait<0>();
    __syncthreads();

    if (k0 > qmax) continue;

    uint4 qa[2][4];
    #pragma unroll
    for (int m = 0; m < 2; m++)
      #pragma unroll
      for (int ks = 0; ks < 4; ks++)
        qa[m][ks] = *(const uint4*)&QF[(((w * 2 + m) * 4 + ks) * 128) + lane * 4];

    float s[2][8][4];
    #pragma unroll
    for (int m = 0; m < 2; m++)
      #pragma unroll
      for (int nt = 0; nt < 8; nt++)
        s[m][nt][0] = s[m][nt][1] = s[m][nt][2] = s[m][nt][3] = 0.0f;

    #pragma unroll
    for (int nt = 0; nt < 8; nt++) {
      uint4 kr0, kr1;
      ldsm4(kr0, KtB[buf] + kb_lane + (uint32_t)(nt * 8 * 144));
      ldsm4(kr1, KtB[buf] + kb_lane + (uint32_t)(nt * 8 * 144 + 64));
      uint2 bk[4] = { make_uint2(kr0.x, kr0.y), make_uint2(kr0.z, kr0.w),
                      make_uint2(kr1.x, kr1.y), make_uint2(kr1.z, kr1.w) };
      #pragma unroll
      for (int ks = 0; ks < 4; ks++) {
        mma_f16(s[0][nt], qa[0][ks], bk[ks]);
        mma_f16(s[1][nt], qa[1][ks], bk[ks]);
      }
    }

    if (k0 + 63 > qmin) {
      #pragma unroll
      for (int m = 0; m < 2; m++) {
        #pragma unroll
        for (int nt = 0; nt < 8; nt++) {
          int c0 = k0 + 8 * nt + 2 * tq;
          int c1 = c0 + 1;
          if (c0 > qg[m])     s[m][nt][0] = -1e30f;
          if (c1 > qg[m])     s[m][nt][1] = -1e30f;
          if (c0 > qg[m] + 8) s[m][nt][2] = -1e30f;
          if (c1 > qg[m] + 8) s[m][nt][3] = -1e30f;
        }
      }
    }

    #pragma unroll
    for (int m = 0; m < 2; m++) {
      float mx0 = -1e30f, mx1 = -1e30f;
      #pragma unroll
      for (int nt = 0; nt < 8; nt++) {
        mx0 = fmaxf(mx0, fmaxf(s[m][nt][0], s[m][nt][1]));
        mx1 = fmaxf(mx1, fmaxf(s[m][nt][2], s[m][nt][3]));
      }
      mx0 = fmaxf(mx0, __shfl_xor_sync(0xffffffffu, mx0, 1));
      mx0 = fmaxf(mx0, __shfl_xor_sync(0xffffffffu, mx0, 2));
      mx1 = fmaxf(mx1, __shfl_xor_sync(0xffffffffu, mx1, 1));
      mx1 = fmaxf(mx1, __shfl_xor_sync(0xffffffffu, mx1, 2));

      float mn0 = fmaxf(mrow[m][0], mx0), mn1 = fmaxf(mrow[m][1], mx1);
      float a0 = __expf(mrow[m][0] - mn0), a1 = __expf(mrow[m][1] - mn1);
      mrow[m][0] = mn0; mrow[m][1] = mn1;

      const int prow = w * 32 + m * 16 + r0;
      float rs0 = 0.0f, rs1 = 0.0f;
      #pragma unroll
      for (int nt = 0; nt < 8; nt++) {
        float p0 = __expf(s[m][nt][0] - mn0);
        float p1 = __expf(s[m][nt][1] - mn0);
        float p2 = __expf(s[m][nt][2] - mn1);
        float p3 = __expf(s[m][nt][3] - mn1);
        rs0 += p0 + p1;
        rs1 += p2 + p3;
        *(uint32_t*)(fsm + FPS_B + prow * 144 + (8 * nt + 2 * tq) * 2) = f2h2(p0, p1);
        *(uint32_t*)(fsm + FPS_B + (prow + 8) * 144 + (8 * nt + 2 * tq) * 2) = f2h2(p2, p3);
      }
      rs0 += __shfl_xor_sync(0xffffffffu, rs0, 1);
      rs0 += __shfl_xor_sync(0xffffffffu, rs0, 2);
      rs1 += __shfl_xor_sync(0xffffffffu, rs1, 1);
      rs1 += __shfl_xor_sync(0xffffffffu, rs1, 2);
      lrow[m][0] = lrow[m][0] * a0 + rs0;
      lrow[m][1] = lrow[m][1] * a1 + rs1;
      #pragma unroll
      for (int nt = 0; nt < 8; nt++) {
        o[m][nt][0] *= a0; o[m][nt][1] *= a0;
        o[m][nt][2] *= a1; o[m][nt][3] *= a1;
      }
    }

    __syncwarp();

    #pragma unroll
    for (int ks = 0; ks < 4; ks++) {
      uint4 pa0, pa1;
      ldsm4(pa0, PsB + pa_lane + (uint32_t)((w * 32) * 144 + ks * 32));
      ldsm4(pa1, PsB + pa_lane + (uint32_t)((w * 32 + 16) * 144 + ks * 32));
      #pragma unroll
      for (int j = 0; j < 4; j++) {
        uint4 vr;
        ldsm4t(vr, VsB[buf] + vb_lane + (uint32_t)(16 * ks * 144 + j * 32));
        uint2 bv0 = make_uint2(vr.x, vr.y);
        uint2 bv1 = make_uint2(vr.z, vr.w);
        mma_f16(o[0][2*j],     pa0, bv0);
        mma_f16(o[0][2*j + 1], pa0, bv1);
        mma_f16(o[1][2*j],     pa1, bv0);
        mma_f16(o[1][2*j + 1], pa1, bv1);
      }
    }
  }

  #pragma unroll
  for (int m = 0; m < 2; m++) {
    float inv0 = 1.0f / lrow[m][0], inv1 = 1.0f / lrow[m][1];
    __half* orow0 = out + ((size_t)b * SEQ + q0 + w * 32 + m * 16 + r0) * EMBED + h * HDIM;
    __half* orow1 = orow0 + (size_t)8 * EMBED;
    #pragma unroll
    for (int nt = 0; nt < 8; nt++) {
      *(uint32_t*)(orow0 + 8 * nt + 2 * tq) =
          f2h2(o[m][nt][0] * inv0, o[m][nt][1] * inv0);
      *(uint32_t*)(orow1 + 8 * nt + 2 * tq) =
          f2h2(o[m][nt][2] * inv1, o[m][nt][3] * inv1);
    }
  }
}

// ---------------------------------------------------------------------------
extern "C" void kernel_launch(void* const* d_in, const int* in_sizes, int n_in,
                              void* d_out, int out_size)
{
  (void)in_sizes; (void)n_in; (void)out_size;
  const float* x     = (const float*)d_in[0];
  const float* qkv_w = (const float*)d_in[1];
  const float* qkv_b = (const float*)d_in[2];
  const float* out_w = (const float*)d_in[3];
  const float* out_b = (const float*)d_in[4];
  float* y = (float*)d_out;

  __half *hx, *hwq, *hwo, *hqkv, *hatt;
  cudaGetSymbolAddress((void**)&hx,   g_hx);
  cudaGetSymbolAddress((void**)&hwq,  g_hw_qkv);
  cudaGetSymbolAddress((void**)&hwo,  g_hw_out);
  cudaGetSymbolAddress((void**)&hqkv, g_hqkv);
  cudaGetSymbolAddress((void**)&hatt, g_hatt);

  cudaFuncSetAttribute(gemm_h<true>,
                       cudaFuncAttributeMaxDynamicSharedMemorySize, GSMEM_BYTES);
  cudaFuncSetAttribute(gemm_h<false>,
                       cudaFuncAttributeMaxDynamicSharedMemorySize, GSMEM_BYTES);
  cudaFuncSetAttribute(flash_h,
                       cudaFuncAttributeMaxDynamicSharedMemorySize, FTOT_B);

  // 0) fp32 -> fp16 conversions
  {
    int n4x = MTOT * EMBED / 4;
    f2h_kernel<<<(n4x + 255) / 256, 256>>>((const float4*)x, (uint2*)hx, n4x);
    int n4q = QKVF * EMBED / 4;
    f2h_kernel<<<(n4q + 255) / 256, 256>>>((const float4*)qkv_w, (uint2*)hwq, n4q);
    int n4o = EMBED * EMBED / 4;
    f2h_kernel<<<(n4o + 255) / 256, 256>>>((const float4*)out_w, (uint2*)hwo, n4o);
  }

  // 1) QKV projection (fp16 in, fp16 out)
  gemm_h<true><<<dim3(QKVF/128, MTOT/128), 128, GSMEM_BYTES>>>(
      hx, hwq, qkv_b, hqkv, MTOT, QKVF, EMBED);
  // 2) Causal flash attention (fp16 I/O, fp32 softmax)
  flash_h<<<dim3(SEQ/128, BATCH*NHEAD), 128, FTOT_B>>>(hqkv, hatt);
  // 3) Output projection (fp16 in, fp32 out)
  gemm_h<false><<<dim3(EMBED/128, MTOT/128), 128, GSMEM_BYTES>>>(
      hatt, hwo, out_b, y, MTOT, EMBED, EMBED);
}